// round 13
// baseline (speedup 1.0000x reference)
#include <cuda_runtime.h>
#include <cuda_fp16.h>
#include <cuda_bf16.h>
#include <cstdint>
#include <math.h>

#define MDIM 16
#define KDIM 4096
#define NDIM 11008
#define GRP 128
#define NGROUPS 32           // KDIM / GRP
#define NTILE 32             // N rows per block (4 n8-cols)
#define NCOL 4               // mma n8-columns per warp
#define NWARP 4              // warps per block, each owns K/4
#define KPW 1024             // K per warp
#define NSTAGE 16            // k64 stages per warp
#define QSTAGE 3             // cp.async ring depth
#define STAGE_BYTES 4096     // 32 rows * 128B
#define NCHUNKS 128          // KDIM/32 k32 chunks

// dynamic smem layout
#define SM_QBUF 0                                   // 4 warps * 3 * 4096 = 49152
#define SM_P    (NWARP * QSTAGE * STAGE_BYTES)      // 49152, 32*32 half2 = 4096
#define SM_RED  (SM_P + NGROUPS * NTILE * 4)        // 53248, 4*16*33*4 = 8448
#define SM_TOTAL (SM_RED + NWARP * MDIM * (NTILE + 1) * 4)   // 61696

__device__ int g_dtype;                               // 0=fp16 1=bf16 2=f32
__device__ __align__(16) uint4 g_Aperm[NCHUNKS * 64]; // [chunk][2][32] fragment-ordered A (fp16)

// ---------------- dtype-generic helpers ----------------

template <int DT>
__device__ __forceinline__ float elt_to_f(const void* p, int i) {
    if (DT == 0) return __half2float(((const __half*)p)[i]);
    if (DT == 1) return __bfloat162float(((const __nv_bfloat16*)p)[i]);
    return ((const float*)p)[i];
}

__device__ __forceinline__ uint32_t bf2_to_h2(uint32_t b) {
    __nv_bfloat162 bb = *reinterpret_cast<__nv_bfloat162*>(&b);
    float2 f = __bfloat1622float2(bb);
    __half2 h = __float22half2_rn(f);
    return *reinterpret_cast<uint32_t*>(&h);
}

template <int DT>
__device__ __forceinline__ uint4 load8h(const void* p, int i) {
    if (DT == 0) {
        return __ldg(reinterpret_cast<const uint4*>((const __half*)p + i));
    } else if (DT == 1) {
        uint4 v = __ldg(reinterpret_cast<const uint4*>((const __nv_bfloat16*)p + i));
        uint4 r;
        r.x = bf2_to_h2(v.x); r.y = bf2_to_h2(v.y);
        r.z = bf2_to_h2(v.z); r.w = bf2_to_h2(v.w);
        return r;
    } else {
        float4 f0 = __ldg(reinterpret_cast<const float4*>((const float*)p + i));
        float4 f1 = __ldg(reinterpret_cast<const float4*>((const float*)p + i + 4));
        __half2 h0 = __float22half2_rn(make_float2(f0.x, f0.y));
        __half2 h1 = __float22half2_rn(make_float2(f0.z, f0.w));
        __half2 h2 = __float22half2_rn(make_float2(f1.x, f1.y));
        __half2 h3 = __float22half2_rn(make_float2(f1.z, f1.w));
        uint4 r;
        r.x = *reinterpret_cast<uint32_t*>(&h0);
        r.y = *reinterpret_cast<uint32_t*>(&h1);
        r.z = *reinterpret_cast<uint32_t*>(&h2);
        r.w = *reinterpret_cast<uint32_t*>(&h3);
        return r;
    }
}

template <int DT>
__device__ __forceinline__ void store_out(void* p, int i, float v) {
    if (DT == 0)      ((__half*)p)[i] = __float2half(v);
    else if (DT == 1) ((__nv_bfloat16*)p)[i] = __float2bfloat16(v);
    else              ((float*)p)[i] = v;
}

// ---------------- dtype detection (warp-level) ----------------
__device__ __forceinline__ int detect_dtype(const void* scales) {
    const int lane = threadIdx.x & 31;
    uint4 v = __ldg(reinterpret_cast<const uint4*>(scales) + lane);
    uint32_t w[4] = {v.x, v.y, v.z, v.w};
    float s0 = 0.f, s1 = 0.f, s2 = 0.f;
    #pragma unroll
    for (int j = 0; j < 4; ++j) {
        float2 fh = __half22float2(*reinterpret_cast<__half2*>(&w[j]));
        s0 += (isfinite(fh.x) ? fabsf(fh.x) : 1e15f) + (isfinite(fh.y) ? fabsf(fh.y) : 1e15f);
        float2 fb = __bfloat1622float2(*reinterpret_cast<__nv_bfloat162*>(&w[j]));
        s1 += (isfinite(fb.x) ? fabsf(fb.x) : 1e15f) + (isfinite(fb.y) ? fabsf(fb.y) : 1e15f);
        float ff = __uint_as_float(w[j]);
        s2 += (isfinite(ff) ? fabsf(ff) : 1e15f);
    }
    #pragma unroll
    for (int off = 16; off; off >>= 1) {
        s0 += __shfl_xor_sync(0xffffffffu, s0, off);
        s1 += __shfl_xor_sync(0xffffffffu, s1, off);
        s2 += __shfl_xor_sync(0xffffffffu, s2, off);
    }
    float sc0 = fabsf(logf(fmaxf(s0, 1e-30f) / 5.27f));
    float sc1 = fabsf(logf(fmaxf(s1, 1e-30f) / 5.27f));
    float sc2 = fabsf(logf(fmaxf(s2, 1e-30f) / 2.64f));
    const float TH = 1.2f;
    if (sc1 < TH) return 1;
    if (sc0 < TH) return 0;
    if (sc2 < TH) return 2;
    if (sc1 <= sc0 && sc1 <= sc2) return 1;
    return (sc0 <= sc2) ? 0 : 2;
}

// ---------------- prep: dtype + fragment-ordered A ----------------
template <int DT>
__device__ __forceinline__ void prep_body(const void* __restrict__ A) {
    const int it   = blockIdx.x;       // 0..127 (k32 chunk)
    const int lane = threadIdx.x;      // 0..31
    const int t = lane & 3, r = lane >> 2;
    const uint4 alo = load8h<DT>(A, r * KDIM + it * 32 + 8 * t);
    const uint4 ahi = load8h<DT>(A, (r + 8) * KDIM + it * 32 + 8 * t);
    g_Aperm[it * 64 + lane]      = make_uint4(alo.x, ahi.x, alo.y, ahi.y);
    g_Aperm[it * 64 + 32 + lane] = make_uint4(alo.z, ahi.z, alo.w, ahi.w);
}

__global__ void prep_kernel(const void* __restrict__ A, const void* __restrict__ scales) {
    const int dt = detect_dtype(scales);
    if (blockIdx.x == 0 && threadIdx.x == 0) g_dtype = dt;
    if (dt == 1)      prep_body<1>(A);
    else if (dt == 0) prep_body<0>(A);
    else              prep_body<2>(A);
}

// ---------------- core math helpers ----------------

__device__ __forceinline__ uint32_t dec_nib(uint32_t x) {
    uint32_t lo, r;
    asm("lop3.b32 %0, %1, 0x0000000F, 0x64006400, 0xEA;" : "=r"(lo) : "r"(x));
    uint32_t sh = x << 12;
    asm("lop3.b32 %0, %1, %2, 0x000F0000, 0xF8;" : "=r"(r) : "r"(lo), "r"(sh));
    return r;
}

__device__ __forceinline__ uint32_t dq_word(uint32_t dec, __half2 vs, __half2 vmz) {
    const __half2 h1024 = __halves2half2(__ushort_as_half(0x6400), __ushort_as_half(0x6400));
    __half2 hq = __hsub2(*reinterpret_cast<__half2*>(&dec), h1024);
    __half2 w  = __hfma2(hq, vs, vmz);
    return *reinterpret_cast<uint32_t*>(&w);
}

__device__ __forceinline__ void mma_16816(float* c,
                                          uint32_t a0, uint32_t a1, uint32_t a2, uint32_t a3,
                                          uint32_t b0, uint32_t b1) {
    asm volatile("mma.sync.aligned.m16n8k16.row.col.f32.f16.f16.f32 "
                 "{%0,%1,%2,%3}, {%4,%5,%6,%7}, {%8,%9}, {%0,%1,%2,%3};\n"
                 : "+f"(c[0]), "+f"(c[1]), "+f"(c[2]), "+f"(c[3])
                 : "r"(a0), "r"(a1), "r"(a2), "r"(a3), "r"(b0), "r"(b1));
}

__device__ __forceinline__ void cp16(uint32_t dst, const void* src) {
    asm volatile("cp.async.cg.shared.global [%0], [%1], 16;\n" :: "r"(dst), "l"(src));
}
__device__ __forceinline__ void cp_commit() {
    asm volatile("cp.async.commit_group;\n");
}
template <int N>
__device__ __forceinline__ void cp_wait() {
    asm volatile("cp.async.wait_group %0;\n" :: "n"(N));
}
__device__ __forceinline__ uint4 lds128(uint32_t addr) {
    uint4 v;
    asm volatile("ld.shared.v4.u32 {%0,%1,%2,%3}, [%4];"
                 : "=r"(v.x), "=r"(v.y), "=r"(v.z), "=r"(v.w) : "r"(addr));
    return v;
}

// q stage layout (per warp, k64 = 32 ints per row, 32 rows):
//   granule(ci 0..7, row 0..31): addr = ci*512 + ((row ^ ((ci&3)<<1)) << 4)
//   cp instr j (8/stage): rows 4j..4j+3; each row's 128B is one line -> 4 lines/instr
//   read chunk kk, col c: slot = kk*4+t, row = c*8+r -> same formula; the XOR
//   rotate keeps each 8-lane phase on distinct banks.

template <int DT>
__device__ __forceinline__ void gptq_body(const int* __restrict__ qw,
                                          const void* __restrict__ scales,
                                          const void* __restrict__ zeros,
                                          const void* __restrict__ bias,
                                          void* __restrict__ out) {
    extern __shared__ __align__(128) char smem[];
    const int tid  = threadIdx.x;
    const int warp = tid >> 5;
    const int lane = tid & 31;
    const int t    = lane & 3;
    const int r    = lane >> 2;
    const int crow = lane >> 3;     // cp row-within-quad
    const int ci   = lane & 7;      // cp 16B-granule index
    const int n0   = blockIdx.x * NTILE;

    const uint32_t smb = (uint32_t)__cvta_generic_to_shared(smem);
    const uint32_t qsm = smb + SM_QBUF + warp * (QSTAGE * STAGE_BYTES);
    __half2* shp = reinterpret_cast<__half2*>(smem + SM_P);          // [32][32]
    float*   shr = reinterpret_cast<float*>(smem + SM_RED);          // [4][16][33]

    // per-thread cp dst offsets / src base (8 rows-quads per stage)
    uint32_t dsto[8];
    #pragma unroll
    for (int j = 0; j < 8; ++j) {
        const int row = j * 4 + crow;
        dsto[j] = (uint32_t)(ci * 512 + ((row ^ ((ci & 3) << 1)) << 4));
    }
    const int* qbase = qw + (n0 + crow) * (KDIM / 2) + warp * (KPW / 2) + ci * 4;

    // prologue: 2 stages in flight
    #pragma unroll
    for (int s = 0; s < QSTAGE - 1; ++s) {
        const uint32_t sb = qsm + s * STAGE_BYTES;
        #pragma unroll
        for (int j = 0; j < 8; ++j) cp16(sb + dsto[j], qbase + j * (4 * 2048) + s * 32);
        cp_commit();
    }

    // scales/zeros -> smem: (s, -s*z) per (group, n); 1024 coalesced elements
    {
        const int sbase = n0 * NGROUPS;
        #pragma unroll
        for (int jj = 0; jj < 8; ++jj) {
            const int i = tid + jj * 128;        // 0..1023
            const int n = i >> 5;
            const int g = i & 31;
            const float s = elt_to_f<DT>(scales, sbase + i);
            const float z = elt_to_f<DT>(zeros,  sbase + i);
            shp[g * NTILE + n] = __halves2half2(__float2half(s), __float2half(-s * z));
        }
    }
    __syncthreads();

    float acc[NCOL][4];
    #pragma unroll
    for (int c = 0; c < NCOL; ++c)
        #pragma unroll
        for (int i = 0; i < 4; ++i) acc[c][i] = 0.f;

    int ring = 0;
    #pragma unroll 1
    for (int s = 0; s < NSTAGE; ++s) {
        const int gg = warp * 8 + (s >> 1);        // 128-k group = 2 stages
        __half2 vs[NCOL], vmz[NCOL];
        #pragma unroll
        for (int c = 0; c < NCOL; ++c) {
            const __half2 p = shp[gg * NTILE + c * 8 + r];
            vs[c]  = __half2half2(__low2half(p));
            vmz[c] = __half2half2(__high2half(p));
        }

        cp_wait<QSTAGE - 2>();
        __syncwarp();
        const uint32_t sb = qsm + (uint32_t)(ring * STAGE_BYTES);

        #pragma unroll
        for (int kk = 0; kk < 2; ++kk) {
            const int gchunk = warp * 32 + s * 2 + kk;
            const uint4 af0 = __ldg(g_Aperm + gchunk * 64 + lane);
            const uint4 af1 = __ldg(g_Aperm + gchunk * 64 + 32 + lane);

            const uint32_t slotbase = sb + (uint32_t)((kk * 4 + t) * 512);
            const uint32_t rot = (uint32_t)(t << 1);

            #pragma unroll
            for (int c = 0; c < NCOL; ++c) {
                const uint4 q = lds128(slotbase + (((uint32_t)(c * 8 + r) ^ rot) << 4));
                const uint32_t w0 = dq_word(dec_nib(q.x), vs[c], vmz[c]);
                const uint32_t w1 = dq_word(dec_nib(q.y), vs[c], vmz[c]);
                const uint32_t w2 = dq_word(dec_nib(q.z), vs[c], vmz[c]);
                const uint32_t w3 = dq_word(dec_nib(q.w), vs[c], vmz[c]);
                mma_16816(acc[c], af0.x, af0.y, af0.z, af0.w, w0, w1);
                mma_16816(acc[c], af1.x, af1.y, af1.z, af1.w, w2, w3);
            }
        }

        // issue stage s+2
        const int nx = s + QSTAGE - 1;
        if (nx < NSTAGE) {
            int nring = ring + (QSTAGE - 1); if (nring >= QSTAGE) nring -= QSTAGE;
            const uint32_t db = qsm + (uint32_t)(nring * STAGE_BYTES);
            #pragma unroll
            for (int j = 0; j < 8; ++j) cp16(db + dsto[j], qbase + j * (4 * 2048) + nx * 32);
        }
        cp_commit();
        if (++ring == QSTAGE) ring = 0;
    }

    // cross-warp reduction: C frag of col c: m = r/r+8, n = c*8 + 2t(+1)
    {
        float* wr = shr + warp * (MDIM * (NTILE + 1));
        #pragma unroll
        for (int c = 0; c < NCOL; ++c) {
            const int nl = c * 8 + 2 * t;
            wr[r * (NTILE + 1) + nl]           = acc[c][0];
            wr[r * (NTILE + 1) + nl + 1]       = acc[c][1];
            wr[(r + 8) * (NTILE + 1) + nl]     = acc[c][2];
            wr[(r + 8) * (NTILE + 1) + nl + 1] = acc[c][3];
        }
    }
    __syncthreads();

    #pragma unroll
    for (int j = 0; j < 4; ++j) {
        const int idx = tid + j * 128;   // 0..511
        const int m  = idx >> 5;         // 0..15
        const int nl = idx & 31;         // 0..31
        const int o  = m * (NTILE + 1) + nl;
        const int st = MDIM * (NTILE + 1);
        float v = (shr[o] + shr[st + o]) + (shr[2 * st + o] + shr[3 * st + o]);
        v += elt_to_f<DT>(bias, n0 + nl);
        store_out<DT>(out, m * NDIM + n0 + nl, v);
    }
}

__global__ __launch_bounds__(128)
void gptq_main_kernel(const int* __restrict__ qw,
                      const void* __restrict__ scales,
                      const void* __restrict__ zeros,
                      const void* __restrict__ bias,
                      void* __restrict__ out) {
    const int dt = g_dtype;
    if (dt == 1)      gptq_body<1>(qw, scales, zeros, bias, out);
    else if (dt == 0) gptq_body<0>(qw, scales, zeros, bias, out);
    else              gptq_body<2>(qw, scales, zeros, bias, out);
}

extern "C" void kernel_launch(void* const* d_in, const int* in_sizes, int n_in,
                              void* d_out, int out_size) {
    const void* A      = nullptr;
    const int*  qw     = nullptr;
    const void* scales = nullptr;
    const void* zeros  = nullptr;
    const void* bias   = nullptr;

    for (int i = 0; i < n_in; ++i) {
        const int sz = in_sizes[i];
        if (sz == MDIM * KDIM) {                    // 65536
            A = d_in[i];
        } else if (sz == NDIM * (KDIM / 2)) {       // 22544384
            qw = (const int*)d_in[i];
        } else if (sz == NDIM) {                    // 11008
            bias = d_in[i];
        } else if (sz == NDIM * NGROUPS) {          // 352256
            if (!scales) scales = d_in[i];
            else         zeros  = d_in[i];
        }
    }

    cudaFuncSetAttribute(gptq_main_kernel,
                         cudaFuncAttributeMaxDynamicSharedMemorySize, SM_TOTAL);

    prep_kernel<<<NCHUNKS, 32>>>(A, scales);
    gptq_main_kernel<<<NDIM / NTILE, 128, SM_TOTAL>>>(qw, scales, zeros, bias, d_out);
}

// round 14
// speedup vs baseline: 1.0062x; 1.0062x over previous
#include <cuda_runtime.h>
#include <cuda_fp16.h>
#include <cuda_bf16.h>
#include <cstdint>
#include <math.h>

#define MDIM 16
#define KDIM 4096
#define NDIM 11008
#define GRP 128
#define NGROUPS 32           // KDIM / GRP
#define NTILE 32             // N rows per block (4 n8-cols, all warps share)
#define NCOL 4               // mma n8-columns per warp
#define NWARP 8              // warps per block, each owns K/8
#define THREADS 256
#define KPW 512              // K per warp
#define NSTAGE 8             // k64 stages per warp
#define QSTAGE 2             // double buffer
#define STAGE_BYTES 4096     // 32 rows * 128B
#define NCHUNKS 128          // KDIM/32 k32 chunks

// dynamic smem: [0,64K) q ring (8 warps x 2 x 4KB), aliased by reduction
//               [64K, 68K) p = (s, -s*z) per (group, n)
#define SM_P     (NWARP * QSTAGE * STAGE_BYTES)          // 65536
#define SM_TOTAL (SM_P + NGROUPS * NTILE * 4)            // 69632

__device__ int g_dtype;                               // 0=fp16 1=bf16 2=f32
__device__ __align__(16) uint4 g_Aperm[NCHUNKS * 64]; // [chunk][2][32] fragment-ordered A (fp16)

// ---------------- dtype-generic helpers ----------------

template <int DT>
__device__ __forceinline__ float elt_to_f(const void* p, int i) {
    if (DT == 0) return __half2float(((const __half*)p)[i]);
    if (DT == 1) return __bfloat162float(((const __nv_bfloat16*)p)[i]);
    return ((const float*)p)[i];
}

__device__ __forceinline__ uint32_t bf2_to_h2(uint32_t b) {
    __nv_bfloat162 bb = *reinterpret_cast<__nv_bfloat162*>(&b);
    float2 f = __bfloat1622float2(bb);
    __half2 h = __float22half2_rn(f);
    return *reinterpret_cast<uint32_t*>(&h);
}

template <int DT>
__device__ __forceinline__ uint4 load8h(const void* p, int i) {
    if (DT == 0) {
        return __ldg(reinterpret_cast<const uint4*>((const __half*)p + i));
    } else if (DT == 1) {
        uint4 v = __ldg(reinterpret_cast<const uint4*>((const __nv_bfloat16*)p + i));
        uint4 r;
        r.x = bf2_to_h2(v.x); r.y = bf2_to_h2(v.y);
        r.z = bf2_to_h2(v.z); r.w = bf2_to_h2(v.w);
        return r;
    } else {
        float4 f0 = __ldg(reinterpret_cast<const float4*>((const float*)p + i));
        float4 f1 = __ldg(reinterpret_cast<const float4*>((const float*)p + i + 4));
        __half2 h0 = __float22half2_rn(make_float2(f0.x, f0.y));
        __half2 h1 = __float22half2_rn(make_float2(f0.z, f0.w));
        __half2 h2 = __float22half2_rn(make_float2(f1.x, f1.y));
        __half2 h3 = __float22half2_rn(make_float2(f1.z, f1.w));
        uint4 r;
        r.x = *reinterpret_cast<uint32_t*>(&h0);
        r.y = *reinterpret_cast<uint32_t*>(&h1);
        r.z = *reinterpret_cast<uint32_t*>(&h2);
        r.w = *reinterpret_cast<uint32_t*>(&h3);
        return r;
    }
}

template <int DT>
__device__ __forceinline__ void store_out(void* p, int i, float v) {
    if (DT == 0)      ((__half*)p)[i] = __float2half(v);
    else if (DT == 1) ((__nv_bfloat16*)p)[i] = __float2bfloat16(v);
    else              ((float*)p)[i] = v;
}

// ---------------- dtype detection (warp-level) ----------------
__device__ __forceinline__ int detect_dtype(const void* scales) {
    const int lane = threadIdx.x & 31;
    uint4 v = __ldg(reinterpret_cast<const uint4*>(scales) + lane);
    uint32_t w[4] = {v.x, v.y, v.z, v.w};
    float s0 = 0.f, s1 = 0.f, s2 = 0.f;
    #pragma unroll
    for (int j = 0; j < 4; ++j) {
        float2 fh = __half22float2(*reinterpret_cast<__half2*>(&w[j]));
        s0 += (isfinite(fh.x) ? fabsf(fh.x) : 1e15f) + (isfinite(fh.y) ? fabsf(fh.y) : 1e15f);
        float2 fb = __bfloat1622float2(*reinterpret_cast<__nv_bfloat162*>(&w[j]));
        s1 += (isfinite(fb.x) ? fabsf(fb.x) : 1e15f) + (isfinite(fb.y) ? fabsf(fb.y) : 1e15f);
        float ff = __uint_as_float(w[j]);
        s2 += (isfinite(ff) ? fabsf(ff) : 1e15f);
    }
    #pragma unroll
    for (int off = 16; off; off >>= 1) {
        s0 += __shfl_xor_sync(0xffffffffu, s0, off);
        s1 += __shfl_xor_sync(0xffffffffu, s1, off);
        s2 += __shfl_xor_sync(0xffffffffu, s2, off);
    }
    float sc0 = fabsf(logf(fmaxf(s0, 1e-30f) / 5.27f));
    float sc1 = fabsf(logf(fmaxf(s1, 1e-30f) / 5.27f));
    float sc2 = fabsf(logf(fmaxf(s2, 1e-30f) / 2.64f));
    const float TH = 1.2f;
    if (sc1 < TH) return 1;
    if (sc0 < TH) return 0;
    if (sc2 < TH) return 2;
    if (sc1 <= sc0 && sc1 <= sc2) return 1;
    return (sc0 <= sc2) ? 0 : 2;
}

// ---------------- prep: dtype + fragment-ordered A ----------------
template <int DT>
__device__ __forceinline__ void prep_body(const void* __restrict__ A) {
    const int it   = blockIdx.x;       // 0..127 (k32 chunk)
    const int lane = threadIdx.x;      // 0..31
    const int t = lane & 3, r = lane >> 2;
    const uint4 alo = load8h<DT>(A, r * KDIM + it * 32 + 8 * t);
    const uint4 ahi = load8h<DT>(A, (r + 8) * KDIM + it * 32 + 8 * t);
    g_Aperm[it * 64 + lane]      = make_uint4(alo.x, ahi.x, alo.y, ahi.y);
    g_Aperm[it * 64 + 32 + lane] = make_uint4(alo.z, ahi.z, alo.w, ahi.w);
}

__global__ void prep_kernel(const void* __restrict__ A, const void* __restrict__ scales) {
    const int dt = detect_dtype(scales);
    if (blockIdx.x == 0 && threadIdx.x == 0) g_dtype = dt;
    if (dt == 1)      prep_body<1>(A);
    else if (dt == 0) prep_body<0>(A);
    else              prep_body<2>(A);
}

// ---------------- core math helpers ----------------

__device__ __forceinline__ uint32_t dec_nib(uint32_t x) {
    uint32_t lo, r;
    asm("lop3.b32 %0, %1, 0x0000000F, 0x64006400, 0xEA;" : "=r"(lo) : "r"(x));
    uint32_t sh = x << 12;
    asm("lop3.b32 %0, %1, %2, 0x000F0000, 0xF8;" : "=r"(r) : "r"(lo), "r"(sh));
    return r;
}

__device__ __forceinline__ uint32_t dq_word(uint32_t dec, __half2 vs, __half2 vmz) {
    const __half2 h1024 = __halves2half2(__ushort_as_half(0x6400), __ushort_as_half(0x6400));
    __half2 hq = __hsub2(*reinterpret_cast<__half2*>(&dec), h1024);
    __half2 w  = __hfma2(hq, vs, vmz);
    return *reinterpret_cast<uint32_t*>(&w);
}

__device__ __forceinline__ void mma_16816(float* c,
                                          uint32_t a0, uint32_t a1, uint32_t a2, uint32_t a3,
                                          uint32_t b0, uint32_t b1) {
    asm volatile("mma.sync.aligned.m16n8k16.row.col.f32.f16.f16.f32 "
                 "{%0,%1,%2,%3}, {%4,%5,%6,%7}, {%8,%9}, {%0,%1,%2,%3};\n"
                 : "+f"(c[0]), "+f"(c[1]), "+f"(c[2]), "+f"(c[3])
                 : "r"(a0), "r"(a1), "r"(a2), "r"(a3), "r"(b0), "r"(b1));
}

__device__ __forceinline__ void cp16(uint32_t dst, const void* src) {
    asm volatile("cp.async.cg.shared.global [%0], [%1], 16;\n" :: "r"(dst), "l"(src));
}
__device__ __forceinline__ void cp_commit() {
    asm volatile("cp.async.commit_group;\n");
}
template <int N>
__device__ __forceinline__ void cp_wait() {
    asm volatile("cp.async.wait_group %0;\n" :: "n"(N));
}
__device__ __forceinline__ uint4 lds128(uint32_t addr) {
    uint4 v;
    asm volatile("ld.shared.v4.u32 {%0,%1,%2,%3}, [%4];"
                 : "=r"(v.x), "=r"(v.y), "=r"(v.z), "=r"(v.w) : "r"(addr));
    return v;
}

// q stage layout (per warp, k64 = 32 ints per row, 32 rows):
//   granule(ci 0..7, row 0..31): addr = ci*512 + ((row ^ ((ci&3)<<1)) << 4)
//   cp instr j (8/stage): rows 4j..4j+3; each row's 128B = one line -> 4 lines/instr
//   read chunk kk, col c: slot = kk*4+t, row = c*8+r; XOR rotate keeps every
//   8-lane read/store phase on distinct banks (verified layout from R13).

template <int DT>
__device__ __forceinline__ void gptq_body(const int* __restrict__ qw,
                                          const void* __restrict__ scales,
                                          const void* __restrict__ zeros,
                                          const void* __restrict__ bias,
                                          void* __restrict__ out) {
    extern __shared__ __align__(128) char smem[];
    const int tid  = threadIdx.x;
    const int warp = tid >> 5;      // k-eighth index
    const int lane = tid & 31;
    const int t    = lane & 3;
    const int r    = lane >> 2;
    const int crow = lane >> 3;     // cp row-within-quad
    const int ci   = lane & 7;      // cp 16B-granule index
    const int n0   = blockIdx.x * NTILE;

    const uint32_t smb = (uint32_t)__cvta_generic_to_shared(smem);
    const uint32_t qsm = smb + warp * (QSTAGE * STAGE_BYTES);
    __half2* shp = reinterpret_cast<__half2*>(smem + SM_P);          // [32][32]
    float*   shr = reinterpret_cast<float*>(smem);                   // aliases q ring

    // per-thread cp dst offsets (8 row-quads per stage)
    uint32_t dsto[8];
    #pragma unroll
    for (int j = 0; j < 8; ++j) {
        const int row = j * 4 + crow;
        dsto[j] = (uint32_t)(ci * 512 + ((row ^ ((ci & 3) << 1)) << 4));
    }
    // src: row n0 + j*4 + crow, k-eighth offset, granule ci
    const int* qbase = qw + (n0 + crow) * (KDIM / 2) + warp * (KPW / 2) + ci * 4;

    // prologue: stages 0 and 1 in flight (double buffer)
    #pragma unroll
    for (int s = 0; s < 2; ++s) {
        const uint32_t sb = qsm + (uint32_t)(s * STAGE_BYTES);
        #pragma unroll
        for (int j = 0; j < 8; ++j) cp16(sb + dsto[j], qbase + j * (4 * 2048) + s * 32);
        cp_commit();
    }

    // scales/zeros -> smem: (s, -s*z) per (group, n); 1024 coalesced elements
    {
        const int sbase = n0 * NGROUPS;
        #pragma unroll
        for (int jj = 0; jj < 4; ++jj) {
            const int i = tid + jj * THREADS;    // 0..1023
            const int n = i >> 5;
            const int g = i & 31;
            const float s = elt_to_f<DT>(scales, sbase + i);
            const float z = elt_to_f<DT>(zeros,  sbase + i);
            shp[g * NTILE + n] = __halves2half2(__float2half(s), __float2half(-s * z));
        }
    }
    __syncthreads();

    float acc[NCOL][4];
    #pragma unroll
    for (int c = 0; c < NCOL; ++c)
        #pragma unroll
        for (int i = 0; i < 4; ++i) acc[c][i] = 0.f;

    #pragma unroll 1
    for (int s = 0; s < NSTAGE; ++s) {
        const int gg = warp * 4 + (s >> 1);        // 128-k group = 2 stages
        __half2 vs[NCOL], vmz[NCOL];
        #pragma unroll
        for (int c = 0; c < NCOL; ++c) {
            const __half2 p = shp[gg * NTILE + c * 8 + r];
            vs[c]  = __half2half2(__low2half(p));
            vmz[c] = __half2half2(__high2half(p));
        }

        cp_wait<QSTAGE - 1>();      // stage s complete; s+1 may be in flight
        __syncwarp();
        const uint32_t sb = qsm + (uint32_t)((s & 1) * STAGE_BYTES);

        #pragma unroll
        for (int kk = 0; kk < 2; ++kk) {
            const int gchunk = warp * 16 + s * 2 + kk;
            const uint4 af0 = __ldg(g_Aperm + gchunk * 64 + lane);
            const uint4 af1 = __ldg(g_Aperm + gchunk * 64 + 32 + lane);

            const uint32_t slotbase = sb + (uint32_t)((kk * 4 + t) * 512);
            const uint32_t rot = (uint32_t)(t << 1);

            #pragma unroll
            for (int c = 0; c < NCOL; ++c) {
                const uint4 q = lds128(slotbase + (((uint32_t)(c * 8 + r) ^ rot) << 4));
                const uint32_t w0 = dq_word(dec_nib(q.x), vs[c], vmz[c]);
                const uint32_t w1 = dq_word(dec_nib(q.y), vs[c], vmz[c]);
                const uint32_t w2 = dq_word(dec_nib(q.z), vs[c], vmz[c]);
                const uint32_t w3 = dq_word(dec_nib(q.w), vs[c], vmz[c]);
                mma_16816(acc[c], af0.x, af0.y, af0.z, af0.w, w0, w1);
                mma_16816(acc[c], af1.x, af1.y, af1.z, af1.w, w2, w3);
            }
        }

        // refill the buffer just consumed with stage s+2
        const int nx = s + 2;
        if (nx < NSTAGE) {
            const uint32_t db = qsm + (uint32_t)((s & 1) * STAGE_BYTES);
            #pragma unroll
            for (int j = 0; j < 8; ++j) cp16(db + dsto[j], qbase + j * (4 * 2048) + nx * 32);
        }
        cp_commit();
    }

    // all cp.async for this warp are consumed; q ring is dead for everyone
    __syncthreads();

    // cross-warp (k) reduction into smem aliasing the q ring.
    // C frag of col c: m = r / r+8, n = c*8 + 2t (+1)
    {
        float* wr = shr + warp * (MDIM * (NTILE + 1));
        #pragma unroll
        for (int c = 0; c < NCOL; ++c) {
            const int nl = c * 8 + 2 * t;
            wr[r * (NTILE + 1) + nl]           = acc[c][0];
            wr[r * (NTILE + 1) + nl + 1]       = acc[c][1];
            wr[(r + 8) * (NTILE + 1) + nl]     = acc[c][2];
            wr[(r + 8) * (NTILE + 1) + nl + 1] = acc[c][3];
        }
    }
    __syncthreads();

    #pragma unroll
    for (int j = 0; j < 2; ++j) {
        const int idx = tid + j * THREADS;  // 0..511
        const int m  = idx >> 5;            // 0..15
        const int nl = idx & 31;            // 0..31
        const int o  = m * (NTILE + 1) + nl;
        const int st = MDIM * (NTILE + 1);
        float v = 0.f;
        #pragma unroll
        for (int w = 0; w < NWARP; ++w) v += shr[w * st + o];
        v += elt_to_f<DT>(bias, n0 + nl);
        store_out<DT>(out, m * NDIM + n0 + nl, v);
    }
}

__global__ __launch_bounds__(THREADS)
void gptq_main_kernel(const int* __restrict__ qw,
                      const void* __restrict__ scales,
                      const void* __restrict__ zeros,
                      const void* __restrict__ bias,
                      void* __restrict__ out) {
    const int dt = g_dtype;
    if (dt == 1)      gptq_body<1>(qw, scales, zeros, bias, out);
    else if (dt == 0) gptq_body<0>(qw, scales, zeros, bias, out);
    else              gptq_body<2>(qw, scales, zeros, bias, out);
}

extern "C" void kernel_launch(void* const* d_in, const int* in_sizes, int n_in,
                              void* d_out, int out_size) {
    const void* A      = nullptr;
    const int*  qw     = nullptr;
    const void* scales = nullptr;
    const void* zeros  = nullptr;
    const void* bias   = nullptr;

    for (int i = 0; i < n_in; ++i) {
        const int sz = in_sizes[i];
        if (sz == MDIM * KDIM) {                    // 65536
            A = d_in[i];
        } else if (sz == NDIM * (KDIM / 2)) {       // 22544384
            qw = (const int*)d_in[i];
        } else if (sz == NDIM) {                    // 11008
            bias = d_in[i];
        } else if (sz == NDIM * NGROUPS) {          // 352256
            if (!scales) scales = d_in[i];
            else         zeros  = d_in[i];
        }
    }

    cudaFuncSetAttribute(gptq_main_kernel,
                         cudaFuncAttributeMaxDynamicSharedMemorySize, SM_TOTAL);

    prep_kernel<<<NCHUNKS, 32>>>(A, scales);
    gptq_main_kernel<<<NDIM / NTILE, THREADS, SM_TOTAL>>>(qw, scales, zeros, bias, d_out);
}

// round 15
// speedup vs baseline: 1.1311x; 1.1241x over previous
#include <cuda_runtime.h>
#include <cuda_fp16.h>
#include <cuda_bf16.h>
#include <cstdint>
#include <math.h>

#define MDIM 16
#define KDIM 4096
#define NDIM 11008
#define GRP 128
#define NGROUPS 32           // KDIM / GRP
#define NTILE 16             // N rows per block
#define NWARP 4              // warps per block, each owns K/4
#define KPW 1024             // K per warp
#define GPW 8                // 128-k groups per warp
#define NSTAGE 16            // k64 stages per warp
#define QSTAGE 3             // cp.async ring depth
#define STAGE_BYTES 2048     // 16 rows * 128B
#define NCHUNKS 128          // KDIM/32 k32 chunks

__device__ int   g_dtype;                             // 0=fp16 1=bf16 2=f32
__device__ __align__(16) uint4 g_Aperm[NCHUNKS * 64]; // [chunk][2][32] fragment-ordered A (fp16)
__device__ float g_Sg[NGROUPS * MDIM];                // per-(group, m) A sums

// ---------------- dtype-generic helpers ----------------

template <int DT>
__device__ __forceinline__ float elt_to_f(const void* p, int i) {
    if (DT == 0) return __half2float(((const __half*)p)[i]);
    if (DT == 1) return __bfloat162float(((const __nv_bfloat16*)p)[i]);
    return ((const float*)p)[i];
}

__device__ __forceinline__ uint32_t bf2_to_h2(uint32_t b) {
    __nv_bfloat162 bb = *reinterpret_cast<__nv_bfloat162*>(&b);
    float2 f = __bfloat1622float2(bb);
    __half2 h = __float22half2_rn(f);
    return *reinterpret_cast<uint32_t*>(&h);
}

template <int DT>
__device__ __forceinline__ uint4 load8h(const void* p, int i) {
    if (DT == 0) {
        return __ldg(reinterpret_cast<const uint4*>((const __half*)p + i));
    } else if (DT == 1) {
        uint4 v = __ldg(reinterpret_cast<const uint4*>((const __nv_bfloat16*)p + i));
        uint4 r;
        r.x = bf2_to_h2(v.x); r.y = bf2_to_h2(v.y);
        r.z = bf2_to_h2(v.z); r.w = bf2_to_h2(v.w);
        return r;
    } else {
        float4 f0 = __ldg(reinterpret_cast<const float4*>((const float*)p + i));
        float4 f1 = __ldg(reinterpret_cast<const float4*>((const float*)p + i + 4));
        __half2 h0 = __float22half2_rn(make_float2(f0.x, f0.y));
        __half2 h1 = __float22half2_rn(make_float2(f0.z, f0.w));
        __half2 h2 = __float22half2_rn(make_float2(f1.x, f1.y));
        __half2 h3 = __float22half2_rn(make_float2(f1.z, f1.w));
        uint4 r;
        r.x = *reinterpret_cast<uint32_t*>(&h0);
        r.y = *reinterpret_cast<uint32_t*>(&h1);
        r.z = *reinterpret_cast<uint32_t*>(&h2);
        r.w = *reinterpret_cast<uint32_t*>(&h3);
        return r;
    }
}

// sum of 8 consecutive logical elements at index i
template <int DT>
__device__ __forceinline__ float sum8(const void* p, int i) {
    if (DT == 2) {
        float4 f0 = __ldg(reinterpret_cast<const float4*>((const float*)p + i));
        float4 f1 = __ldg(reinterpret_cast<const float4*>((const float*)p + i + 4));
        return ((f0.x + f0.y) + (f0.z + f0.w)) + ((f1.x + f1.y) + (f1.z + f1.w));
    }
    uint4 v = __ldg(reinterpret_cast<const uint4*>((const __half*)p + i));
    uint32_t w[4] = {v.x, v.y, v.z, v.w};
    float s = 0.f;
    #pragma unroll
    for (int j = 0; j < 4; ++j) {
        if (DT == 0) {
            float2 f = __half22float2(*reinterpret_cast<__half2*>(&w[j]));
            s += f.x + f.y;
        } else {
            float2 f = __bfloat1622float2(*reinterpret_cast<__nv_bfloat162*>(&w[j]));
            s += f.x + f.y;
        }
    }
    return s;
}

template <int DT>
__device__ __forceinline__ void store_out(void* p, int i, float v) {
    if (DT == 0)      ((__half*)p)[i] = __float2half(v);
    else if (DT == 1) ((__nv_bfloat16*)p)[i] = __float2bfloat16(v);
    else              ((float*)p)[i] = v;
}

// ---------------- dtype detection (warp-level) ----------------
__device__ __forceinline__ int detect_dtype(const void* scales) {
    const int lane = threadIdx.x & 31;
    uint4 v = __ldg(reinterpret_cast<const uint4*>(scales) + lane);
    uint32_t w[4] = {v.x, v.y, v.z, v.w};
    float s0 = 0.f, s1 = 0.f, s2 = 0.f;
    #pragma unroll
    for (int j = 0; j < 4; ++j) {
        float2 fh = __half22float2(*reinterpret_cast<__half2*>(&w[j]));
        s0 += (isfinite(fh.x) ? fabsf(fh.x) : 1e15f) + (isfinite(fh.y) ? fabsf(fh.y) : 1e15f);
        float2 fb = __bfloat1622float2(*reinterpret_cast<__nv_bfloat162*>(&w[j]));
        s1 += (isfinite(fb.x) ? fabsf(fb.x) : 1e15f) + (isfinite(fb.y) ? fabsf(fb.y) : 1e15f);
        float ff = __uint_as_float(w[j]);
        s2 += (isfinite(ff) ? fabsf(ff) : 1e15f);
    }
    #pragma unroll
    for (int off = 16; off; off >>= 1) {
        s0 += __shfl_xor_sync(0xffffffffu, s0, off);
        s1 += __shfl_xor_sync(0xffffffffu, s1, off);
        s2 += __shfl_xor_sync(0xffffffffu, s2, off);
    }
    float sc0 = fabsf(logf(fmaxf(s0, 1e-30f) / 5.27f));
    float sc1 = fabsf(logf(fmaxf(s1, 1e-30f) / 5.27f));
    float sc2 = fabsf(logf(fmaxf(s2, 1e-30f) / 2.64f));
    const float TH = 1.2f;
    if (sc1 < TH) return 1;
    if (sc0 < TH) return 0;
    if (sc2 < TH) return 2;
    if (sc1 <= sc0 && sc1 <= sc2) return 1;
    return (sc0 <= sc2) ? 0 : 2;
}

// ---------------- prep: dtype + fragment-ordered A + group sums ----------------
template <int DT>
__device__ __forceinline__ void prep_body(const void* __restrict__ A) {
    const int it   = blockIdx.x;       // 0..127 (k32 chunk)
    const int lane = threadIdx.x & 31;
    const int t = lane & 3, r = lane >> 2;
    const uint4 alo = load8h<DT>(A, r * KDIM + it * 32 + 8 * t);
    const uint4 ahi = load8h<DT>(A, (r + 8) * KDIM + it * 32 + 8 * t);
    g_Aperm[it * 64 + lane]      = make_uint4(alo.x, ahi.x, alo.y, ahi.y);
    g_Aperm[it * 64 + 32 + lane] = make_uint4(alo.z, ahi.z, alo.w, ahi.w);
}

template <int DT>
__device__ __forceinline__ void prep_sg(const void* __restrict__ A) {
    const int g = blockIdx.x;          // 0..31
    const int m = threadIdx.x & 31;
    if (m < MDIM) {
        const int base = m * KDIM + g * GRP;
        float s = 0.f;
        #pragma unroll
        for (int i = 0; i < GRP / 8; ++i) s += sum8<DT>(A, base + i * 8);
        g_Sg[g * MDIM + m] = s;
    }
}

__global__ void prep_kernel(const void* __restrict__ A, const void* __restrict__ scales) {
    const int dt = detect_dtype(scales);
    if (blockIdx.x == 0 && threadIdx.x == 0) g_dtype = dt;
    const int warp = threadIdx.x >> 5;
    if (warp == 0) {
        if (dt == 1)      prep_body<1>(A);
        else if (dt == 0) prep_body<0>(A);
        else              prep_body<2>(A);
    } else if (blockIdx.x < NGROUPS) {
        if (dt == 1)      prep_sg<1>(A);
        else if (dt == 0) prep_sg<0>(A);
        else              prep_sg<2>(A);
    }
}

// ---------------- core math helpers ----------------

// dec_nib(x): fp16 pair (1024+lo_nibble, 1024+hi_nibble) as packed bits
__device__ __forceinline__ uint32_t dec_nib(uint32_t x) {
    uint32_t lo, r;
    asm("lop3.b32 %0, %1, 0x0000000F, 0x64006400, 0xEA;" : "=r"(lo) : "r"(x));
    uint32_t sh = x << 12;
    asm("lop3.b32 %0, %1, %2, 0x000F0000, 0xF8;" : "=r"(r) : "r"(lo), "r"(sh));
    return r;
}

__device__ __forceinline__ void mma_16816(float* c,
                                          uint32_t a0, uint32_t a1, uint32_t a2, uint32_t a3,
                                          uint32_t b0, uint32_t b1) {
    asm volatile("mma.sync.aligned.m16n8k16.row.col.f32.f16.f16.f32 "
                 "{%0,%1,%2,%3}, {%4,%5,%6,%7}, {%8,%9}, {%0,%1,%2,%3};\n"
                 : "+f"(c[0]), "+f"(c[1]), "+f"(c[2]), "+f"(c[3])
                 : "r"(a0), "r"(a1), "r"(a2), "r"(a3), "r"(b0), "r"(b1));
}

__device__ __forceinline__ void cp16(uint32_t dst, const void* src) {
    asm volatile("cp.async.cg.shared.global [%0], [%1], 16;\n" :: "r"(dst), "l"(src));
}
__device__ __forceinline__ void cp_commit() {
    asm volatile("cp.async.commit_group;\n");
}
template <int N>
__device__ __forceinline__ void cp_wait() {
    asm volatile("cp.async.wait_group %0;\n" :: "n"(N));
}
__device__ __forceinline__ uint4 lds128(uint32_t addr) {
    uint4 v;
    asm volatile("ld.shared.v4.u32 {%0,%1,%2,%3}, [%4];"
                 : "=r"(v.x), "=r"(v.y), "=r"(v.z), "=r"(v.w) : "r"(addr));
    return v;
}

// shared memory: 24KB qbuf + 2KB S + 2KB U + 4.4KB red = 32.4KB static
__shared__ __align__(128) char sh_q[NWARP][QSTAGE][STAGE_BYTES];
__shared__ float sh_S[NGROUPS][NTILE];            // s per (group, n)
__shared__ float sh_U[NGROUPS][NTILE];            // s*(1024+z) per (group, n)
__shared__ float sh_red[NWARP][MDIM][NTILE + 1];

// q stage layout (per warp, k64 = 32 ints per row, 16 rows) — identical to R10:
//  granule(ci 0..7, row 0..15): addr = ci*256 + ((row ^ ((ci&3)<<1)) << 4)
//  cp instr j (4/stage): rows 4j..4j+3; each row's 128B = one line -> 4 lines/instr
//  read chunk kk, col c: slot = kk*4+t, row = c*8+r; XOR rotate -> conflict-free.

template <int DT>
__device__ __forceinline__ void gptq_body(const int* __restrict__ qw,
                                          const void* __restrict__ scales,
                                          const void* __restrict__ zeros,
                                          const void* __restrict__ bias,
                                          void* __restrict__ out) {
    const int tid  = threadIdx.x;
    const int warp = tid >> 5;
    const int lane = tid & 31;
    const int t    = lane & 3;
    const int r    = lane >> 2;
    const int crow = lane >> 3;     // cp row-within-quad
    const int ci   = lane & 7;      // cp 16B-granule index
    const int n0   = blockIdx.x * NTILE;

    const uint32_t qsm = (uint32_t)__cvta_generic_to_shared(&sh_q[warp][0][0]);

    // per-thread cp dst offsets / src pointers (4 rows per stage)
    uint32_t dsto[4];
    const int* srcp[4];
    #pragma unroll
    for (int j = 0; j < 4; ++j) {
        const int row = j * 4 + crow;
        dsto[j] = (uint32_t)(ci * 256 + ((row ^ ((ci & 3) << 1)) << 4));
        srcp[j] = qw + (n0 + row) * (KDIM / 2) + warp * (KPW / 2) + ci * 4;
    }

    // prologue: 2 stages in flight
    #pragma unroll
    for (int s = 0; s < QSTAGE - 1; ++s) {
        const uint32_t sb = qsm + s * STAGE_BYTES;
        #pragma unroll
        for (int j = 0; j < 4; ++j) cp16(sb + dsto[j], srcp[j] + s * 32);
        cp_commit();
    }

    // scales/zeros -> smem: s and u = s*(1024+z); 512 coalesced elements each
    {
        const int sbase = n0 * NGROUPS;
        #pragma unroll
        for (int jj = 0; jj < 4; ++jj) {
            const int i = tid * 4 + jj;          // 0..511
            const int n = i >> 5;
            const int g = i & 31;
            const float s = elt_to_f<DT>(scales, sbase + i);
            const float z = elt_to_f<DT>(zeros,  sbase + i);
            sh_S[g][n] = s;
            sh_U[g][n] = s * (1024.f + z);
        }
    }
    __syncthreads();

    float acc0[4] = {0.f, 0.f, 0.f, 0.f};
    float acc1[4] = {0.f, 0.f, 0.f, 0.f};

    #pragma unroll 1
    for (int g = 0; g < GPW; ++g) {
        const int gg = warp * GPW + g;
        const float sga = __ldg(g_Sg + gg * MDIM + r);
        const float sgb = __ldg(g_Sg + gg * MDIM + 8 + r);

        float cfr0[4] = {0.f, 0.f, 0.f, 0.f};
        float cfr1[4] = {0.f, 0.f, 0.f, 0.f};

        #pragma unroll
        for (int s2 = 0; s2 < 2; ++s2) {
            const int s = g * 2 + s2;

            cp_wait<QSTAGE - 2>();
            __syncwarp();
            const uint32_t sb = qsm + (uint32_t)((s % QSTAGE) * STAGE_BYTES);

            #pragma unroll
            for (int kk = 0; kk < 2; ++kk) {
                const int gchunk = warp * 32 + s * 2 + kk;
                const uint4 af0 = __ldg(g_Aperm + gchunk * 64 + lane);
                const uint4 af1 = __ldg(g_Aperm + gchunk * 64 + 32 + lane);

                const int slot = kk * 4 + t;
                const uint32_t sw = sb + (uint32_t)(slot * 256);
                const uint32_t rot = (uint32_t)((slot & 3) << 1);
                const uint4 q0 = lds128(sw + (((uint32_t)r ^ rot) << 4));        // col 0 (n=r)
                const uint4 q1 = lds128(sw + (((uint32_t)(8 + r) ^ rot) << 4));  // col 1 (n=8+r)

                // raw accumulate: B = (1024 + q), dequant folded per group
                mma_16816(cfr0, af0.x, af0.y, af0.z, af0.w, dec_nib(q0.x), dec_nib(q0.y));
                mma_16816(cfr0, af1.x, af1.y, af1.z, af1.w, dec_nib(q0.z), dec_nib(q0.w));
                mma_16816(cfr1, af0.x, af0.y, af0.z, af0.w, dec_nib(q1.x), dec_nib(q1.y));
                mma_16816(cfr1, af1.x, af1.y, af1.z, af1.w, dec_nib(q1.z), dec_nib(q1.w));
            }

            // issue stage s+2 (empty commit keeps group count invariant)
            const int nx = s + QSTAGE - 1;
            if (nx < NSTAGE) {
                const uint32_t db = qsm + (uint32_t)((nx % QSTAGE) * STAGE_BYTES);
                #pragma unroll
                for (int j = 0; j < 4; ++j) cp16(db + dsto[j], srcp[j] + nx * 32);
            }
            cp_commit();
        }

        // fold: acc += s*cfr - u*Sg   (exact dequant of the whole group)
        {
            const int nl0 = 2 * t;         // col 0 columns
            const int nl1 = 8 + 2 * t;     // col 1 columns
            const float s00 = sh_S[gg][nl0],     s01 = sh_S[gg][nl0 + 1];
            const float u00 = sh_U[gg][nl0],     u01 = sh_U[gg][nl0 + 1];
            const float s10 = sh_S[gg][nl1],     s11 = sh_S[gg][nl1 + 1];
            const float u10 = sh_U[gg][nl1],     u11 = sh_U[gg][nl1 + 1];
            acc0[0] += s00 * cfr0[0] - u00 * sga;
            acc0[1] += s01 * cfr0[1] - u01 * sga;
            acc0[2] += s00 * cfr0[2] - u00 * sgb;
            acc0[3] += s01 * cfr0[3] - u01 * sgb;
            acc1[0] += s10 * cfr1[0] - u10 * sga;
            acc1[1] += s11 * cfr1[1] - u11 * sga;
            acc1[2] += s10 * cfr1[2] - u10 * sgb;
            acc1[3] += s11 * cfr1[3] - u11 * sgb;
        }
    }

    // cross-warp reduction: C frag (m = r/r+8, n = c*8 + 2t, 2t+1)
    {
        sh_red[warp][r][2 * t]             = acc0[0];
        sh_red[warp][r][2 * t + 1]         = acc0[1];
        sh_red[warp][r + 8][2 * t]         = acc0[2];
        sh_red[warp][r + 8][2 * t + 1]     = acc0[3];
        sh_red[warp][r][8 + 2 * t]         = acc1[0];
        sh_red[warp][r][8 + 2 * t + 1]     = acc1[1];
        sh_red[warp][r + 8][8 + 2 * t]     = acc1[2];
        sh_red[warp][r + 8][8 + 2 * t + 1] = acc1[3];
    }
    __syncthreads();

    #pragma unroll
    for (int j = 0; j < 2; ++j) {
        const int idx = tid + j * 128;   // 0..255
        const int m  = idx >> 4;         // 0..15
        const int nl = idx & 15;         // 0..15
        float v = (sh_red[0][m][nl] + sh_red[1][m][nl]) + (sh_red[2][m][nl] + sh_red[3][m][nl]);
        v += elt_to_f<DT>(bias, n0 + nl);
        store_out<DT>(out, m * NDIM + n0 + nl, v);
    }
}

__global__ __launch_bounds__(128, 5)
void gptq_main_kernel(const int* __restrict__ qw,
                      const void* __restrict__ scales,
                      const void* __restrict__ zeros,
                      const void* __restrict__ bias,
                      void* __restrict__ out) {
    const int dt = g_dtype;
    if (dt == 1)      gptq_body<1>(qw, scales, zeros, bias, out);
    else if (dt == 0) gptq_body<0>(qw, scales, zeros, bias, out);
    else              gptq_body<2>(qw, scales, zeros, bias, out);
}

extern "C" void kernel_launch(void* const* d_in, const int* in_sizes, int n_in,
                              void* d_out, int out_size) {
    const void* A      = nullptr;
    const int*  qw     = nullptr;
    const void* scales = nullptr;
    const void* zeros  = nullptr;
    const void* bias   = nullptr;

    for (int i = 0; i < n_in; ++i) {
        const int sz = in_sizes[i];
        if (sz == MDIM * KDIM) {                    // 65536
            A = d_in[i];
        } else if (sz == NDIM * (KDIM / 2)) {       // 22544384
            qw = (const int*)d_in[i];
        } else if (sz == NDIM) {                    // 11008
            bias = d_in[i];
        } else if (sz == NDIM * NGROUPS) {          // 352256
            if (!scales) scales = d_in[i];
            else         zeros  = d_in[i];
        }
    }

    prep_kernel<<<NCHUNKS, 64>>>(A, scales);
    gptq_main_kernel<<<NDIM / NTILE, 128>>>(qw, scales, zeros, bias, d_out);
}